// round 15
// baseline (speedup 1.0000x reference)
#include <cuda_runtime.h>
#include <cuda_bf16.h>
#include <cstdint>

#define B_   8
#define S_   1024
#define DM_  512
#define H_   8
#define DK_  64
#define SP   1028   // sS row stride in words

static const size_t ROWS_   = (size_t)B_ * S_;
static const size_t LN_N_   = ROWS_ * DM_;
static const size_t ATTN_N_ = (size_t)B_*H_*S_*S_;
static const size_t MASK_N_ = (size_t)B_*S_*S_;

// ---------------- device scratch ----------------------------------------------
__device__ float g_Q  [8192*512];
__device__ float g_K  [8192*512];
__device__ float g_V  [8192*512];
__device__ float g_ctx[8192*512];
__device__ float g_pre[8192*512];
__device__ float g_attn_scratch[67108864ull];
__device__ unsigned char g_mask[8*1024*1024];
__device__ int g_mask_is_u8;

// ---------------- helpers ------------------------------------------------------
__device__ __forceinline__ uint32_t f2tf(float f) {
    uint32_t r;
    asm("cvt.rna.tf32.f32 %0, %1;" : "=r"(r) : "f"(f));
    return r;
}
// pack (lo, hi) floats -> bf16x2 word: d<15:0>=lo, d<31:16>=hi
__device__ __forceinline__ uint32_t pk2(float lo, float hi) {
    uint32_t r;
    asm("cvt.rn.bf16x2.f32 %0, %1, %2;" : "=r"(r) : "f"(hi), "f"(lo));
    return r;
}

// MUFU-free exp: n = rint(x*log2e); 2^f via deg-5 Taylor (|f*ln2|<=0.347,
// rel err ~2e-6); scale by exponent-bit construction. All fma/alu pipe.
__device__ __forceinline__ float fexp(float x) {
    float t = x * 1.4426950408889634f;
    float n = rintf(t);
    float y = (t - n) * 0.6931471805599453f;
    float p = 1.0f + y * (1.0f + y * (0.5f + y * (0.16666667f +
              y * (0.041666667f + y * 0.0083333333f))));
    return p * __int_as_float(((int)n + 127) << 23);
}

__device__ __forceinline__ void mma8(float* c, const uint32_t* a, uint32_t b0, uint32_t b1) {
    asm volatile("mma.sync.aligned.m16n8k8.row.col.f32.tf32.tf32.f32 "
        "{%0,%1,%2,%3}, {%4,%5,%6,%7}, {%8,%9}, {%0,%1,%2,%3};"
        : "+f"(c[0]), "+f"(c[1]), "+f"(c[2]), "+f"(c[3])
        : "r"(a[0]), "r"(a[1]), "r"(a[2]), "r"(a[3]), "r"(b0), "r"(b1));
}
__device__ __forceinline__ void mma16bf(float* c, const uint32_t* a, uint32_t b0, uint32_t b1) {
    asm volatile("mma.sync.aligned.m16n8k16.row.col.f32.bf16.bf16.f32 "
        "{%0,%1,%2,%3}, {%4,%5,%6,%7}, {%8,%9}, {%0,%1,%2,%3};"
        : "+f"(c[0]), "+f"(c[1]), "+f"(c[2]), "+f"(c[3])
        : "r"(a[0]), "r"(a[1]), "r"(a[2]), "r"(a[3]), "r"(b0), "r"(b1));
}

// ---------------- mask dtype detection + normalization ------------------------
__global__ void mask_detect_kernel(const unsigned char* __restrict__ m) {
    __shared__ int cnt;
    if (threadIdx.x == 0) cnt = 0;
    __syncthreads();
    int local = 0;
    for (int i = threadIdx.x; i < 65536; i += 256)
        if ((i & 3) && __ldg(&m[i])) local++;
    if (local) atomicAdd(&cnt, local);
    __syncthreads();
    if (threadIdx.x == 0) g_mask_is_u8 = (cnt > 0) ? 1 : 0;
}

__global__ void mask_convert_kernel(const unsigned char* __restrict__ m) {
    const int u8 = g_mask_is_u8;
    size_t i = (size_t)blockIdx.x * blockDim.x + threadIdx.x;
    if (i < MASK_N_) {
        if (u8) g_mask[i] = (__ldg(&m[i]) != 0);
        else    g_mask[i] = (__ldg(&((const int*)m)[i]) != 0);
    }
}

// ---------------- tf32 tensor-core GEMM with register-staged prefetch ---------
__global__ __launch_bounds__(256)
void gemm_tc(const float* __restrict__ A0, const float* __restrict__ A1, const float* __restrict__ A2,
             const float* __restrict__ B0, const float* __restrict__ B1, const float* __restrict__ B2,
             const float* __restrict__ R,
             float* __restrict__ C0, float* __restrict__ C1, float* __restrict__ C2,
             int addResid)
{
    const float* A  = (blockIdx.z == 0) ? A0 : (blockIdx.z == 1) ? A1 : A2;
    const float* Bm = (blockIdx.z == 0) ? B0 : (blockIdx.z == 1) ? B1 : B2;
    float*       C  = (blockIdx.z == 0) ? C0 : (blockIdx.z == 1) ? C1 : C2;

    __shared__ uint32_t As[128 * 36];
    __shared__ uint32_t Bs[32 * 132];
    const int t = threadIdx.x;
    const int w = t >> 5, lane = t & 31, gid = lane >> 2, tid4 = lane & 3;
    const int wm = w & 1, wn = w >> 1;
    const int brow = blockIdx.y * 128, bcol = blockIdx.x * 128;

    float acc[4][4][4];
    #pragma unroll
    for (int mt = 0; mt < 4; mt++)
        #pragma unroll
        for (int nt = 0; nt < 4; nt++)
            #pragma unroll
            for (int i = 0; i < 4; i++) acc[mt][nt][i] = 0.f;

    float4 va[4], vb[4];
    #pragma unroll
    for (int i = 0; i < 4; i++) {
        int idx = i * 256 + t;
        int m = idx >> 3, k4 = (idx & 7) * 4;
        va[i] = *(const float4*)&A[(size_t)(brow + m) * 512 + k4];
        int kr = idx >> 5, nc = (idx & 31) * 4;
        vb[i] = *(const float4*)&Bm[(size_t)kr * 512 + bcol + nc];
    }

    for (int k0 = 0; k0 < 512; k0 += 32) {
        #pragma unroll
        for (int i = 0; i < 4; i++) {
            int idx = i * 256 + t;
            int m = idx >> 3, k4 = (idx & 7) * 4;
            *(uint4*)&As[m * 36 + k4] =
                make_uint4(f2tf(va[i].x), f2tf(va[i].y), f2tf(va[i].z), f2tf(va[i].w));
            int kr = idx >> 5, nc = (idx & 31) * 4;
            *(uint4*)&Bs[kr * 132 + nc] =
                make_uint4(f2tf(vb[i].x), f2tf(vb[i].y), f2tf(vb[i].z), f2tf(vb[i].w));
        }
        __syncthreads();
        if (k0 + 32 < 512) {
            #pragma unroll
            for (int i = 0; i < 4; i++) {
                int idx = i * 256 + t;
                int m = idx >> 3, k4 = (idx & 7) * 4;
                va[i] = *(const float4*)&A[(size_t)(brow + m) * 512 + k0 + 32 + k4];
                int kr = idx >> 5, nc = (idx & 31) * 4;
                vb[i] = *(const float4*)&Bm[(size_t)(k0 + 32 + kr) * 512 + bcol + nc];
            }
        }
        #pragma unroll
        for (int kk = 0; kk < 4; kk++) {
            const int kb = kk * 8;
            uint32_t af[4][4];
            #pragma unroll
            for (int mt = 0; mt < 4; mt++) {
                int row = wm * 64 + mt * 16 + gid;
                af[mt][0] = As[row * 36 + kb + tid4];
                af[mt][1] = As[(row + 8) * 36 + kb + tid4];
                af[mt][2] = As[row * 36 + kb + tid4 + 4];
                af[mt][3] = As[(row + 8) * 36 + kb + tid4 + 4];
            }
            uint32_t bf[4][2];
            #pragma unroll
            for (int nt = 0; nt < 4; nt++) {
                int n = wn * 32 + nt * 8 + gid;
                bf[nt][0] = Bs[(kb + tid4) * 132 + n];
                bf[nt][1] = Bs[(kb + tid4 + 4) * 132 + n];
            }
            #pragma unroll
            for (int mt = 0; mt < 4; mt++)
                #pragma unroll
                for (int nt = 0; nt < 4; nt++)
                    mma8(acc[mt][nt], af[mt], bf[nt][0], bf[nt][1]);
        }
        __syncthreads();
    }

    #pragma unroll
    for (int mt = 0; mt < 4; mt++) {
        #pragma unroll
        for (int nt = 0; nt < 4; nt++) {
            size_t row = (size_t)(brow + wm * 64 + mt * 16 + gid);
            size_t col = (size_t)(bcol + wn * 32 + nt * 8 + 2 * tid4);
            float2 v0 = make_float2(acc[mt][nt][0], acc[mt][nt][1]);
            float2 v1 = make_float2(acc[mt][nt][2], acc[mt][nt][3]);
            if (addResid) {
                float2 r0 = *(const float2*)&R[row * 512 + col];
                float2 r1 = *(const float2*)&R[(row + 8) * 512 + col];
                v0.x += r0.x; v0.y += r0.y; v1.x += r1.x; v1.y += r1.y;
            }
            *(float2*)&C[row * 512 + col] = v0;
            *(float2*)&C[(row + 8) * 512 + col] = v1;
        }
    }
}

// ---------------- fused attention v9: v8 + MUFU-free exp ----------------------
// block = (b, h, 32 q rows), 512 threads / 16 warps, 1 CTA/SM
// Phase 1: S=QK^T tf32, fexp (fma-pipe), row sums, E stored tf32 in sS
// Phase 2: normalize: attn=E*rinv (fp32 STG) + pack P bf16x2 in-place into sS
// Phase 3: ctx = P@V with bf16 m16n8k16; V packed (k,k+1)/word, [128][72]
__global__ __launch_bounds__(512)
void attn_kernel(const float* __restrict__ Q, const float* __restrict__ K,
                 const float* __restrict__ V,
                 float* __restrict__ attn, float* __restrict__ ctx)
{
    extern __shared__ float sm[];
    float*    sS  = sm;                               // 32*1028 (E tf32 -> P bf16x2)
    uint32_t* sSu = (uint32_t*)sm;
    uint32_t* sKV = (uint32_t*)(sm + 32 * SP);        // K [256][68]; later V2 [128][72]
    uint32_t* sV2 = sKV;
    uint32_t* sQ  = sKV + 256 * 68;                   // [32][68]
    float*    sSum  = (float*)(sQ + 32 * 68);         // [32][9]
    float*    sRinv = sSum + 32 * 9;                  // [32]
    float*    sRed  = (float*)sKV;                    // reduce overlay

    const int t = threadIdx.x;
    const int w = t >> 5, lane = t & 31, gid = lane >> 2, t4 = lane & 3;
    const int b = blockIdx.z, h = blockIdx.y;
    const int q0 = blockIdx.x * 32;
    const size_t rowbase = (size_t)b * 1024;
    const float* Qb = Q + (rowbase + q0) * 512 + h * 64;
    const float* Kb = K + rowbase * 512 + h * 64;
    const float* Vb = V + rowbase * 512 + h * 64;
    const unsigned char* mb = g_mask + ((size_t)b * 1024 + q0) * 1024;

    // load Q tile 32x64 -> tf32
    {
        int r = t >> 4, j = (t & 15) * 4;
        float4 v = *(const float4*)&Qb[(size_t)r * 512 + j];
        *(uint4*)&sQ[r * 68 + j] = make_uint4(f2tf(v.x), f2tf(v.y), f2tf(v.z), f2tf(v.w));
    }
    __syncthreads();

    const int wm = w & 1;      // 16-row half
    const int wn = w >> 1;     // 0..7, 32-col slice (phase 1)
    const int arow = wm * 16 + gid;
    float rs0 = 0.f, rs1 = 0.f;

    // ---- Phase 1: scores -> fexp -> rowsum, E stored tf32 ----
    for (int ch = 0; ch < 4; ch++) {
        const int s0 = ch * 256;
        __syncthreads();
        #pragma unroll
        for (int p = 0; p < 8; p++) {
            int idx = p * 512 + t;
            int r = idx >> 4, j = (idx & 15) * 4;
            float4 v = *(const float4*)&Kb[(size_t)(s0 + r) * 512 + j];
            *(uint4*)&sKV[r * 68 + j] = make_uint4(f2tf(v.x), f2tf(v.y), f2tf(v.z), f2tf(v.w));
        }
        __syncthreads();
        uchar2 mk0[4], mk1[4];
        #pragma unroll
        for (int nt = 0; nt < 4; nt++) {
            int col = s0 + wn * 32 + nt * 8 + 2 * t4;
            mk0[nt] = *(const uchar2*)&mb[(size_t)arow * 1024 + col];
            mk1[nt] = *(const uchar2*)&mb[(size_t)(arow + 8) * 1024 + col];
        }
        float acc[4][4];
        #pragma unroll
        for (int nt = 0; nt < 4; nt++)
            #pragma unroll
            for (int i = 0; i < 4; i++) acc[nt][i] = 0.f;
        #pragma unroll
        for (int ks = 0; ks < 8; ks++) {
            const int k0 = ks * 8;
            uint32_t af[4];
            af[0] = sQ[arow * 68 + k0 + t4];
            af[1] = sQ[(arow + 8) * 68 + k0 + t4];
            af[2] = sQ[arow * 68 + k0 + t4 + 4];
            af[3] = sQ[(arow + 8) * 68 + k0 + t4 + 4];
            #pragma unroll
            for (int nt = 0; nt < 4; nt++) {
                int n = wn * 32 + nt * 8 + gid;
                uint32_t b0 = sKV[n * 68 + k0 + t4];
                uint32_t b1 = sKV[n * 68 + k0 + t4 + 4];
                mma8(acc[nt], af, b0, b1);
            }
        }
        #pragma unroll
        for (int nt = 0; nt < 4; nt++) {
            int col = s0 + wn * 32 + nt * 8 + 2 * t4;
            float e0 = mk0[nt].x ? 0.f : fexp(acc[nt][0] * 0.125f);
            float e1 = mk0[nt].y ? 0.f : fexp(acc[nt][1] * 0.125f);
            float e2 = mk1[nt].x ? 0.f : fexp(acc[nt][2] * 0.125f);
            float e3 = mk1[nt].y ? 0.f : fexp(acc[nt][3] * 0.125f);
            rs0 += e0 + e1;
            rs1 += e2 + e3;
            *(uint2*)&sSu[arow * SP + col]       = make_uint2(f2tf(e0), f2tf(e1));
            *(uint2*)&sSu[(arow + 8) * SP + col] = make_uint2(f2tf(e2), f2tf(e3));
        }
    }
    __syncthreads();

    // ---- row sums ----
    rs0 += __shfl_xor_sync(0xffffffffu, rs0, 1);
    rs0 += __shfl_xor_sync(0xffffffffu, rs0, 2);
    rs1 += __shfl_xor_sync(0xffffffffu, rs1, 1);
    rs1 += __shfl_xor_sync(0xffffffffu, rs1, 2);
    if (t4 == 0) {
        sSum[arow * 9 + wn]       = rs0;
        sSum[(arow + 8) * 9 + wn] = rs1;
    }
    __syncthreads();
    if (t < 32) {
        float s = 0.f;
        #pragma unroll
        for (int j = 0; j < 8; j++) s += sSum[t * 9 + j];
        sRinv[t] = 1.0f / s;
    }
    __syncthreads();

    // ---- Phase 2: normalize -> attn (fp32) + pack P bf16x2 in-place ----
    #pragma unroll
    for (int ri = 0; ri < 2; ri++) {
        int r = w * 2 + ri;
        float rv = sRinv[r];
        float* srow = &sS[r * SP];
        uint32_t* srowu = &sSu[r * SP];
        float* arowp = attn + ((size_t)(b * 8 + h) * 1024 + q0 + r) * 1024;
        #pragma unroll
        for (int j = 0; j < 8; j++) {
            int c4 = lane + j * 32;
            float4 v = *(float4*)&srow[c4 * 4];
            v.x *= rv; v.y *= rv; v.z *= rv; v.w *= rv;
            *(float4*)&arowp[c4 * 4] = v;
            *(uint2*)&srowu[c4 * 2] = make_uint2(pk2(v.x, v.y), pk2(v.z, v.w));
        }
    }

    // ---- Phase 3: ctx = P @ V, bf16 m16n8k16, 16x32 tiles, 4-way k-split ----
    {
        const int wn3 = (w >> 1) & 1;  // 32-col half of 64
        const int kq  = w >> 2;        // kv quarter of each 256-chunk
        float acc2[4][4];
        #pragma unroll
        for (int nt = 0; nt < 4; nt++)
            #pragma unroll
            for (int i = 0; i < 4; i++) acc2[nt][i] = 0.f;

        for (int ch = 0; ch < 4; ch++) {
            const int s0 = ch * 256;
            __syncthreads();
            #pragma unroll
            for (int p = 0; p < 4; p++) {
                int idx = p * 512 + t;
                int k2 = idx >> 4, j = (idx & 15) * 4;
                float4 v0 = *(const float4*)&Vb[(size_t)(s0 + 2 * k2) * 512 + j];
                float4 v1 = *(const float4*)&Vb[(size_t)(s0 + 2 * k2 + 1) * 512 + j];
                *(uint4*)&sV2[k2 * 72 + j] = make_uint4(
                    pk2(v0.x, v1.x), pk2(v0.y, v1.y), pk2(v0.z, v1.z), pk2(v0.w, v1.w));
            }
            __syncthreads();
            const int s0w = ch * 128;
            #pragma unroll
            for (int ks = 0; ks < 4; ks++) {
                const int wA  = s0w + kq * 32 + ks * 8;
                const int klw = kq * 32 + ks * 8;
                uint32_t af[4];
                af[0] = sSu[arow * SP + wA + t4];
                af[1] = sSu[(arow + 8) * SP + wA + t4];
                af[2] = sSu[arow * SP + wA + 4 + t4];
                af[3] = sSu[(arow + 8) * SP + wA + 4 + t4];
                #pragma unroll
                for (int nt = 0; nt < 4; nt++) {
                    int n = wn3 * 32 + nt * 8 + gid;
                    uint32_t b0 = sV2[(klw + t4) * 72 + n];
                    uint32_t b1 = sV2[(klw + 4 + t4) * 72 + n];
                    mma16bf(acc2[nt], af, b0, b1);
                }
            }
        }
        __syncthreads();
        if (kq > 0) {
            int slot = ((kq - 1) * 4 + wm * 2 + wn3) * 544 + lane * 17;
            #pragma unroll
            for (int nt = 0; nt < 4; nt++)
                #pragma unroll
                for (int i = 0; i < 4; i++)
                    sRed[slot + nt * 4 + i] = acc2[nt][i];
        }
        __syncthreads();
        if (kq == 0) {
            #pragma unroll
            for (int q = 1; q < 4; q++) {
                int slot = ((q - 1) * 4 + wm * 2 + wn3) * 544 + lane * 17;
                #pragma unroll
                for (int nt = 0; nt < 4; nt++)
                    #pragma unroll
                    for (int i = 0; i < 4; i++)
                        acc2[nt][i] += sRed[slot + nt * 4 + i];
            }
            float* cb = ctx + (rowbase + q0) * 512 + h * 64;
            #pragma unroll
            for (int nt = 0; nt < 4; nt++) {
                int col = wn3 * 32 + nt * 8 + 2 * t4;
                *(float2*)&cb[(size_t)arow * 512 + col] =
                    make_float2(acc2[nt][0], acc2[nt][1]);
                *(float2*)&cb[(size_t)(arow + 8) * 512 + col] =
                    make_float2(acc2[nt][2], acc2[nt][3]);
            }
        }
    }
}

// ---------------- LayerNorm -----------------------------------------------------
__global__ __launch_bounds__(128)
void ln_kernel(const float* __restrict__ X, const float* __restrict__ gamma,
               const float* __restrict__ beta, float* __restrict__ out)
{
    __shared__ float red[8];
    const int row = blockIdx.x, t = threadIdx.x;
    const float* x = X + (size_t)row * 512;
    float4 v = *(const float4*)&x[t * 4];
    float s  = (v.x + v.y) + (v.z + v.w);
    float s2 = v.x * v.x + v.y * v.y + v.z * v.z + v.w * v.w;
    #pragma unroll
    for (int o = 16; o > 0; o >>= 1) {
        s  += __shfl_xor_sync(0xffffffffu, s,  o);
        s2 += __shfl_xor_sync(0xffffffffu, s2, o);
    }
    const int warp = t >> 5, lane = t & 31;
    if (lane == 0) { red[warp] = s; red[4 + warp] = s2; }
    __syncthreads();
    s  = red[0] + red[1] + red[2] + red[3];
    s2 = red[4] + red[5] + red[6] + red[7];
    float mean = s * (1.0f / 512.0f);
    float var  = s2 * (1.0f / 512.0f) - mean * mean;
    float rstd = rsqrtf(var + 1e-5f);
    float4 gv = *(const float4*)&gamma[t * 4];
    float4 bv = *(const float4*)&beta[t * 4];
    float4 o4;
    o4.x = (v.x - mean) * rstd * gv.x + bv.x;
    o4.y = (v.y - mean) * rstd * gv.y + bv.y;
    o4.z = (v.z - mean) * rstd * gv.z + bv.z;
    o4.w = (v.w - mean) * rstd * gv.w + bv.w;
    *(float4*)&out[(size_t)row * 512 + t * 4] = o4;
}

// ---------------- launch ------------------------------------------------------
extern "C" void kernel_launch(void* const* d_in, const int* in_sizes, int n_in,
                              void* d_out, int out_size)
{
    const float* iQ   = (const float*)d_in[0];
    const float* iK   = (const float*)d_in[1];
    const float* iV   = (const float*)d_in[2];
    const unsigned char* maskRaw = (const unsigned char*)d_in[3];
    const float* WQ   = (const float*)d_in[4];
    const float* WK   = (const float*)d_in[5];
    const float* WV   = (const float*)d_in[6];
    const float* Wfc  = (const float*)d_in[7];
    const float* gam  = (const float*)d_in[8];
    const float* bet  = (const float*)d_in[9];

    float *gq, *gk, *gv, *gctx, *gpre, *gattn;
    cudaGetSymbolAddress((void**)&gq,    g_Q);
    cudaGetSymbolAddress((void**)&gk,    g_K);
    cudaGetSymbolAddress((void**)&gv,    g_V);
    cudaGetSymbolAddress((void**)&gctx,  g_ctx);
    cudaGetSymbolAddress((void**)&gpre,  g_pre);
    cudaGetSymbolAddress((void**)&gattn, g_attn_scratch);

    float* out = (float*)d_out;
    float* out_ln;
    float* out_attn;
    size_t os = (size_t)out_size;
    if (os >= LN_N_ + ATTN_N_)      { out_ln = out;   out_attn = out + LN_N_; }
    else if (os == ATTN_N_)         { out_attn = out; out_ln = gq; }
    else                            { out_ln = out;   out_attn = gattn; }

    mask_detect_kernel<<<1, 256>>>(maskRaw);
    mask_convert_kernel<<<(int)((MASK_N_ + 255) / 256), 256>>>(maskRaw);

    // fused QKV projections
    gemm_tc<<<dim3(4, 64, 3), 256>>>(iQ, iK, iV, WQ, WK, WV, nullptr, gq, gk, gv, 0);

    // fused attention (32 q rows, 512 threads, bf16-k16 P@V, fma-pipe exp)
    const int smemBytes = (32 * SP + 256 * 68 + 32 * 68 + 32 * 9 + 32) * 4;  // 211232
    cudaFuncSetAttribute(attn_kernel, cudaFuncAttributeMaxDynamicSharedMemorySize, smemBytes);
    attn_kernel<<<dim3(32, 8, 8), 512, smemBytes>>>(gq, gk, gv, out_attn, gctx);

    // output projection + residual
    gemm_tc<<<dim3(4, 64, 1), 256>>>(gctx, nullptr, nullptr, Wfc, nullptr, nullptr,
                                     iQ, gpre, nullptr, nullptr, 1);

    ln_kernel<<<8192, 128>>>(gpre, gam, bet, out_ln);
}

// round 16
// speedup vs baseline: 1.1348x; 1.1348x over previous
#include <cuda_runtime.h>
#include <cuda_bf16.h>
#include <cstdint>

#define B_   8
#define S_   1024
#define DM_  512
#define H_   8
#define DK_  64
#define SP   1028   // sS row stride in words

static const size_t ROWS_   = (size_t)B_ * S_;
static const size_t LN_N_   = ROWS_ * DM_;
static const size_t ATTN_N_ = (size_t)B_*H_*S_*S_;
static const size_t MASK_N_ = (size_t)B_*S_*S_;

// ---------------- device scratch ----------------------------------------------
__device__ float g_Q  [8192*512];
__device__ float g_K  [8192*512];
__device__ float g_V  [8192*512];
__device__ float g_ctx[8192*512];
__device__ float g_pre[8192*512];
__device__ float g_attn_scratch[67108864ull];
__device__ unsigned char g_mask[8*1024*1024];
__device__ int g_mask_is_u8;

// ---------------- helpers ------------------------------------------------------
__device__ __forceinline__ uint32_t f2tf(float f) {
    uint32_t r;
    asm("cvt.rna.tf32.f32 %0, %1;" : "=r"(r) : "f"(f));
    return r;
}
// pack (lo, hi) floats -> bf16x2 word: d<15:0>=lo, d<31:16>=hi
__device__ __forceinline__ uint32_t pk2(float lo, float hi) {
    uint32_t r;
    asm("cvt.rn.bf16x2.f32 %0, %1, %2;" : "=r"(r) : "f"(hi), "f"(lo));
    return r;
}

__device__ __forceinline__ void mma8(float* c, const uint32_t* a, uint32_t b0, uint32_t b1) {
    asm volatile("mma.sync.aligned.m16n8k8.row.col.f32.tf32.tf32.f32 "
        "{%0,%1,%2,%3}, {%4,%5,%6,%7}, {%8,%9}, {%0,%1,%2,%3};"
        : "+f"(c[0]), "+f"(c[1]), "+f"(c[2]), "+f"(c[3])
        : "r"(a[0]), "r"(a[1]), "r"(a[2]), "r"(a[3]), "r"(b0), "r"(b1));
}
__device__ __forceinline__ void mma16bf(float* c, const uint32_t* a, uint32_t b0, uint32_t b1) {
    asm volatile("mma.sync.aligned.m16n8k16.row.col.f32.bf16.bf16.f32 "
        "{%0,%1,%2,%3}, {%4,%5,%6,%7}, {%8,%9}, {%0,%1,%2,%3};"
        : "+f"(c[0]), "+f"(c[1]), "+f"(c[2]), "+f"(c[3])
        : "r"(a[0]), "r"(a[1]), "r"(a[2]), "r"(a[3]), "r"(b0), "r"(b1));
}

// ---------------- mask dtype detection + normalization ------------------------
__global__ void mask_detect_kernel(const unsigned char* __restrict__ m) {
    __shared__ int cnt;
    if (threadIdx.x == 0) cnt = 0;
    __syncthreads();
    int local = 0;
    for (int i = threadIdx.x; i < 65536; i += 256)
        if ((i & 3) && __ldg(&m[i])) local++;
    if (local) atomicAdd(&cnt, local);
    __syncthreads();
    if (threadIdx.x == 0) g_mask_is_u8 = (cnt > 0) ? 1 : 0;
}

__global__ void mask_convert_kernel(const unsigned char* __restrict__ m) {
    const int u8 = g_mask_is_u8;
    size_t i = (size_t)blockIdx.x * blockDim.x + threadIdx.x;
    if (i < MASK_N_) {
        if (u8) g_mask[i] = (__ldg(&m[i]) != 0);
        else    g_mask[i] = (__ldg(&((const int*)m)[i]) != 0);
    }
}

// ---------------- tf32 tensor-core GEMM, 2 CTAs/SM -----------------------------
__global__ __launch_bounds__(256, 2)
void gemm_tc(const float* __restrict__ A0, const float* __restrict__ A1, const float* __restrict__ A2,
             const float* __restrict__ B0, const float* __restrict__ B1, const float* __restrict__ B2,
             const float* __restrict__ R,
             float* __restrict__ C0, float* __restrict__ C1, float* __restrict__ C2,
             int addResid)
{
    const float* A  = (blockIdx.z == 0) ? A0 : (blockIdx.z == 1) ? A1 : A2;
    const float* Bm = (blockIdx.z == 0) ? B0 : (blockIdx.z == 1) ? B1 : B2;
    float*       C  = (blockIdx.z == 0) ? C0 : (blockIdx.z == 1) ? C1 : C2;

    __shared__ uint32_t As[128 * 36];
    __shared__ uint32_t Bs[32 * 132];
    const int t = threadIdx.x;
    const int w = t >> 5, lane = t & 31, gid = lane >> 2, tid4 = lane & 3;
    const int wm = w & 1, wn = w >> 1;
    const int brow = blockIdx.y * 128, bcol = blockIdx.x * 128;

    float acc[4][4][4];
    #pragma unroll
    for (int mt = 0; mt < 4; mt++)
        #pragma unroll
        for (int nt = 0; nt < 4; nt++)
            #pragma unroll
            for (int i = 0; i < 4; i++) acc[mt][nt][i] = 0.f;

    float4 va[4], vb[4];
    #pragma unroll
    for (int i = 0; i < 4; i++) {
        int idx = i * 256 + t;
        int m = idx >> 3, k4 = (idx & 7) * 4;
        va[i] = *(const float4*)&A[(size_t)(brow + m) * 512 + k4];
        int kr = idx >> 5, nc = (idx & 31) * 4;
        vb[i] = *(const float4*)&Bm[(size_t)kr * 512 + bcol + nc];
    }

    for (int k0 = 0; k0 < 512; k0 += 32) {
        #pragma unroll
        for (int i = 0; i < 4; i++) {
            int idx = i * 256 + t;
            int m = idx >> 3, k4 = (idx & 7) * 4;
            *(uint4*)&As[m * 36 + k4] =
                make_uint4(f2tf(va[i].x), f2tf(va[i].y), f2tf(va[i].z), f2tf(va[i].w));
            int kr = idx >> 5, nc = (idx & 31) * 4;
            *(uint4*)&Bs[kr * 132 + nc] =
                make_uint4(f2tf(vb[i].x), f2tf(vb[i].y), f2tf(vb[i].z), f2tf(vb[i].w));
        }
        __syncthreads();
        if (k0 + 32 < 512) {
            #pragma unroll
            for (int i = 0; i < 4; i++) {
                int idx = i * 256 + t;
                int m = idx >> 3, k4 = (idx & 7) * 4;
                va[i] = *(const float4*)&A[(size_t)(brow + m) * 512 + k0 + 32 + k4];
                int kr = idx >> 5, nc = (idx & 31) * 4;
                vb[i] = *(const float4*)&Bm[(size_t)(k0 + 32 + kr) * 512 + bcol + nc];
            }
        }
        #pragma unroll
        for (int kk = 0; kk < 4; kk++) {
            const int kb = kk * 8;
            uint32_t af[4][4];
            #pragma unroll
            for (int mt = 0; mt < 4; mt++) {
                int row = wm * 64 + mt * 16 + gid;
                af[mt][0] = As[row * 36 + kb + tid4];
                af[mt][1] = As[(row + 8) * 36 + kb + tid4];
                af[mt][2] = As[row * 36 + kb + tid4 + 4];
                af[mt][3] = As[(row + 8) * 36 + kb + tid4 + 4];
            }
            uint32_t bf[4][2];
            #pragma unroll
            for (int nt = 0; nt < 4; nt++) {
                int n = wn * 32 + nt * 8 + gid;
                bf[nt][0] = Bs[(kb + tid4) * 132 + n];
                bf[nt][1] = Bs[(kb + tid4 + 4) * 132 + n];
            }
            #pragma unroll
            for (int mt = 0; mt < 4; mt++)
                #pragma unroll
                for (int nt = 0; nt < 4; nt++)
                    mma8(acc[mt][nt], af[mt], bf[nt][0], bf[nt][1]);
        }
        __syncthreads();
    }

    #pragma unroll
    for (int mt = 0; mt < 4; mt++) {
        #pragma unroll
        for (int nt = 0; nt < 4; nt++) {
            size_t row = (size_t)(brow + wm * 64 + mt * 16 + gid);
            size_t col = (size_t)(bcol + wn * 32 + nt * 8 + 2 * tid4);
            float2 v0 = make_float2(acc[mt][nt][0], acc[mt][nt][1]);
            float2 v1 = make_float2(acc[mt][nt][2], acc[mt][nt][3]);
            if (addResid) {
                float2 r0 = *(const float2*)&R[row * 512 + col];
                float2 r1 = *(const float2*)&R[(row + 8) * 512 + col];
                v0.x += r0.x; v0.y += r0.y; v1.x += r1.x; v1.y += r1.y;
            }
            *(float2*)&C[row * 512 + col] = v0;
            *(float2*)&C[(row + 8) * 512 + col] = v1;
        }
    }
}

// ---------------- fused attention (exact R14 config: best attn = 398 us) ------
// block = (b, h, 32 q rows), 512 threads / 16 warps, 1 CTA/SM
// Phase 1: S=QK^T tf32, __expf (no max), row sums, E stored tf32 in sS
// Phase 2: normalize: attn=E*rinv (fp32 STG) + pack P bf16x2 in-place into sS
// Phase 3: ctx = P@V with bf16 m16n8k16; V packed (k,k+1)/word, [128][72]
__global__ __launch_bounds__(512)
void attn_kernel(const float* __restrict__ Q, const float* __restrict__ K,
                 const float* __restrict__ V,
                 float* __restrict__ attn, float* __restrict__ ctx)
{
    extern __shared__ float sm[];
    float*    sS  = sm;                               // 32*1028 (E tf32 -> P bf16x2)
    uint32_t* sSu = (uint32_t*)sm;
    uint32_t* sKV = (uint32_t*)(sm + 32 * SP);        // K [256][68]; later V2 [128][72]
    uint32_t* sV2 = sKV;
    uint32_t* sQ  = sKV + 256 * 68;                   // [32][68]
    float*    sSum  = (float*)(sQ + 32 * 68);         // [32][9]
    float*    sRinv = sSum + 32 * 9;                  // [32]
    float*    sRed  = (float*)sKV;                    // reduce overlay

    const int t = threadIdx.x;
    const int w = t >> 5, lane = t & 31, gid = lane >> 2, t4 = lane & 3;
    const int b = blockIdx.z, h = blockIdx.y;
    const int q0 = blockIdx.x * 32;
    const size_t rowbase = (size_t)b * 1024;
    const float* Qb = Q + (rowbase + q0) * 512 + h * 64;
    const float* Kb = K + rowbase * 512 + h * 64;
    const float* Vb = V + rowbase * 512 + h * 64;
    const unsigned char* mb = g_mask + ((size_t)b * 1024 + q0) * 1024;

    // load Q tile 32x64 -> tf32
    {
        int r = t >> 4, j = (t & 15) * 4;
        float4 v = *(const float4*)&Qb[(size_t)r * 512 + j];
        *(uint4*)&sQ[r * 68 + j] = make_uint4(f2tf(v.x), f2tf(v.y), f2tf(v.z), f2tf(v.w));
    }
    __syncthreads();

    const int wm = w & 1;      // 16-row half
    const int wn = w >> 1;     // 0..7, 32-col slice (phase 1)
    const int arow = wm * 16 + gid;
    float rs0 = 0.f, rs1 = 0.f;

    // ---- Phase 1: scores -> exp -> rowsum, E stored tf32 ----
    for (int ch = 0; ch < 4; ch++) {
        const int s0 = ch * 256;
        __syncthreads();
        #pragma unroll
        for (int p = 0; p < 8; p++) {
            int idx = p * 512 + t;
            int r = idx >> 4, j = (idx & 15) * 4;
            float4 v = *(const float4*)&Kb[(size_t)(s0 + r) * 512 + j];
            *(uint4*)&sKV[r * 68 + j] = make_uint4(f2tf(v.x), f2tf(v.y), f2tf(v.z), f2tf(v.w));
        }
        __syncthreads();
        uchar2 mk0[4], mk1[4];
        #pragma unroll
        for (int nt = 0; nt < 4; nt++) {
            int col = s0 + wn * 32 + nt * 8 + 2 * t4;
            mk0[nt] = *(const uchar2*)&mb[(size_t)arow * 1024 + col];
            mk1[nt] = *(const uchar2*)&mb[(size_t)(arow + 8) * 1024 + col];
        }
        float acc[4][4];
        #pragma unroll
        for (int nt = 0; nt < 4; nt++)
            #pragma unroll
            for (int i = 0; i < 4; i++) acc[nt][i] = 0.f;
        #pragma unroll
        for (int ks = 0; ks < 8; ks++) {
            const int k0 = ks * 8;
            uint32_t af[4];
            af[0] = sQ[arow * 68 + k0 + t4];
            af[1] = sQ[(arow + 8) * 68 + k0 + t4];
            af[2] = sQ[arow * 68 + k0 + t4 + 4];
            af[3] = sQ[(arow + 8) * 68 + k0 + t4 + 4];
            #pragma unroll
            for (int nt = 0; nt < 4; nt++) {
                int n = wn * 32 + nt * 8 + gid;
                uint32_t b0 = sKV[n * 68 + k0 + t4];
                uint32_t b1 = sKV[n * 68 + k0 + t4 + 4];
                mma8(acc[nt], af, b0, b1);
            }
        }
        #pragma unroll
        for (int nt = 0; nt < 4; nt++) {
            int col = s0 + wn * 32 + nt * 8 + 2 * t4;
            float e0 = mk0[nt].x ? 0.f : __expf(acc[nt][0] * 0.125f);
            float e1 = mk0[nt].y ? 0.f : __expf(acc[nt][1] * 0.125f);
            float e2 = mk1[nt].x ? 0.f : __expf(acc[nt][2] * 0.125f);
            float e3 = mk1[nt].y ? 0.f : __expf(acc[nt][3] * 0.125f);
            rs0 += e0 + e1;
            rs1 += e2 + e3;
            *(uint2*)&sSu[arow * SP + col]       = make_uint2(f2tf(e0), f2tf(e1));
            *(uint2*)&sSu[(arow + 8) * SP + col] = make_uint2(f2tf(e2), f2tf(e3));
        }
    }
    __syncthreads();

    // ---- row sums ----
    rs0 += __shfl_xor_sync(0xffffffffu, rs0, 1);
    rs0 += __shfl_xor_sync(0xffffffffu, rs0, 2);
    rs1 += __shfl_xor_sync(0xffffffffu, rs1, 1);
    rs1 += __shfl_xor_sync(0xffffffffu, rs1, 2);
    if (t4 == 0) {
        sSum[arow * 9 + wn]       = rs0;
        sSum[(arow + 8) * 9 + wn] = rs1;
    }
    __syncthreads();
    if (t < 32) {
        float s = 0.f;
        #pragma unroll
        for (int j = 0; j < 8; j++) s += sSum[t * 9 + j];
        sRinv[t] = 1.0f / s;
    }
    __syncthreads();

    // ---- Phase 2: normalize -> attn (fp32) + pack P bf16x2 in-place ----
    #pragma unroll
    for (int ri = 0; ri < 2; ri++) {
        int r = w * 2 + ri;
        float rv = sRinv[r];
        float* srow = &sS[r * SP];
        uint32_t* srowu = &sSu[r * SP];
        float* arowp = attn + ((size_t)(b * 8 + h) * 1024 + q0 + r) * 1024;
        #pragma unroll
        for (int j = 0; j < 8; j++) {
            int c4 = lane + j * 32;
            float4 v = *(float4*)&srow[c4 * 4];
            v.x *= rv; v.y *= rv; v.z *= rv; v.w *= rv;
            *(float4*)&arowp[c4 * 4] = v;
            *(uint2*)&srowu[c4 * 2] = make_uint2(pk2(v.x, v.y), pk2(v.z, v.w));
        }
    }

    // ---- Phase 3: ctx = P @ V, bf16 m16n8k16, 16x32 tiles, 4-way k-split ----
    {
        const int wn3 = (w >> 1) & 1;  // 32-col half of 64
        const int kq  = w >> 2;        // kv quarter of each 256-chunk
        float acc2[4][4];
        #pragma unroll
        for (int nt = 0; nt < 4; nt++)
            #pragma unroll
            for (int i = 0; i < 4; i++) acc2[nt][i] = 0.f;

        for (int ch = 0; ch < 4; ch++) {
            const int s0 = ch * 256;
            __syncthreads();
            #pragma unroll
            for (int p = 0; p < 4; p++) {
                int idx = p * 512 + t;
                int k2 = idx >> 4, j = (idx & 15) * 4;
                float4 v0 = *(const float4*)&Vb[(size_t)(s0 + 2 * k2) * 512 + j];
                float4 v1 = *(const float4*)&Vb[(size_t)(s0 + 2 * k2 + 1) * 512 + j];
                *(uint4*)&sV2[k2 * 72 + j] = make_uint4(
                    pk2(v0.x, v1.x), pk2(v0.y, v1.y), pk2(v0.z, v1.z), pk2(v0.w, v1.w));
            }
            __syncthreads();
            const int s0w = ch * 128;
            #pragma unroll
            for (int ks = 0; ks < 4; ks++) {
                const int wA  = s0w + kq * 32 + ks * 8;
                const int klw = kq * 32 + ks * 8;
                uint32_t af[4];
                af[0] = sSu[arow * SP + wA + t4];
                af[1] = sSu[(arow + 8) * SP + wA + t4];
                af[2] = sSu[arow * SP + wA + 4 + t4];
                af[3] = sSu[(arow + 8) * SP + wA + 4 + t4];
                #pragma unroll
                for (int nt = 0; nt < 4; nt++) {
                    int n = wn3 * 32 + nt * 8 + gid;
                    uint32_t b0 = sV2[(klw + t4) * 72 + n];
                    uint32_t b1 = sV2[(klw + 4 + t4) * 72 + n];
                    mma16bf(acc2[nt], af, b0, b1);
                }
            }
        }
        __syncthreads();
        if (kq > 0) {
            int slot = ((kq - 1) * 4 + wm * 2 + wn3) * 544 + lane * 17;
            #pragma unroll
            for (int nt = 0; nt < 4; nt++)
                #pragma unroll
                for (int i = 0; i < 4; i++)
                    sRed[slot + nt * 4 + i] = acc2[nt][i];
        }
        __syncthreads();
        if (kq == 0) {
            #pragma unroll
            for (int q = 1; q < 4; q++) {
                int slot = ((q - 1) * 4 + wm * 2 + wn3) * 544 + lane * 17;
                #pragma unroll
                for (int nt = 0; nt < 4; nt++)
                    #pragma unroll
                    for (int i = 0; i < 4; i++)
                        acc2[nt][i] += sRed[slot + nt * 4 + i];
            }
            float* cb = ctx + (rowbase + q0) * 512 + h * 64;
            #pragma unroll
            for (int nt = 0; nt < 4; nt++) {
                int col = wn3 * 32 + nt * 8 + 2 * t4;
                *(float2*)&cb[(size_t)arow * 512 + col] =
                    make_float2(acc2[nt][0], acc2[nt][1]);
                *(float2*)&cb[(size_t)(arow + 8) * 512 + col] =
                    make_float2(acc2[nt][2], acc2[nt][3]);
            }
        }
    }
}

// ---------------- LayerNorm -----------------------------------------------------
__global__ __launch_bounds__(128)
void ln_kernel(const float* __restrict__ X, const float* __restrict__ gamma,
               const float* __restrict__ beta, float* __restrict__ out)
{
    __shared__ float red[8];
    const int row = blockIdx.x, t = threadIdx.x;
    const float* x = X + (size_t)row * 512;
    float4 v = *(const float4*)&x[t * 4];
    float s  = (v.x + v.y) + (v.z + v.w);
    float s2 = v.x * v.x + v.y * v.y + v.z * v.z + v.w * v.w;
    #pragma unroll
    for (int o = 16; o > 0; o >>= 1) {
        s  += __shfl_xor_sync(0xffffffffu, s,  o);
        s2 += __shfl_xor_sync(0xffffffffu, s2, o);
    }
    const int warp = t >> 5, lane = t & 31;
    if (lane == 0) { red[warp] = s; red[4 + warp] = s2; }
    __syncthreads();
    s  = red[0] + red[1] + red[2] + red[3];
    s2 = red[4] + red[5] + red[6] + red[7];
    float mean = s * (1.0f / 512.0f);
    float var  = s2 * (1.0f / 512.0f) - mean * mean;
    float rstd = rsqrtf(var + 1e-5f);
    float4 gv = *(const float4*)&gamma[t * 4];
    float4 bv = *(const float4*)&beta[t * 4];
    float4 o4;
    o4.x = (v.x - mean) * rstd * gv.x + bv.x;
    o4.y = (v.y - mean) * rstd * gv.y + bv.y;
    o4.z = (v.z - mean) * rstd * gv.z + bv.z;
    o4.w = (v.w - mean) * rstd * gv.w + bv.w;
    *(float4*)&out[(size_t)row * 512 + t * 4] = o4;
}

// ---------------- launch ------------------------------------------------------
extern "C" void kernel_launch(void* const* d_in, const int* in_sizes, int n_in,
                              void* d_out, int out_size)
{
    const float* iQ   = (const float*)d_in[0];
    const float* iK   = (const float*)d_in[1];
    const float* iV   = (const float*)d_in[2];
    const unsigned char* maskRaw = (const unsigned char*)d_in[3];
    const float* WQ   = (const float*)d_in[4];
    const float* WK   = (const float*)d_in[5];
    const float* WV   = (const float*)d_in[6];
    const float* Wfc  = (const float*)d_in[7];
    const float* gam  = (const float*)d_in[8];
    const float* bet  = (const float*)d_in[9];

    float *gq, *gk, *gv, *gctx, *gpre, *gattn;
    cudaGetSymbolAddress((void**)&gq,    g_Q);
    cudaGetSymbolAddress((void**)&gk,    g_K);
    cudaGetSymbolAddress((void**)&gv,    g_V);
    cudaGetSymbolAddress((void**)&gctx,  g_ctx);
    cudaGetSymbolAddress((void**)&gpre,  g_pre);
    cudaGetSymbolAddress((void**)&gattn, g_attn_scratch);

    float* out = (float*)d_out;
    float* out_ln;
    float* out_attn;
    size_t os = (size_t)out_size;
    if (os >= LN_N_ + ATTN_N_)      { out_ln = out;   out_attn = out + LN_N_; }
    else if (os == ATTN_N_)         { out_attn = out; out_ln = gq; }
    else                            { out_ln = out;   out_attn = gattn; }

    mask_detect_kernel<<<1, 256>>>(maskRaw);
    mask_convert_kernel<<<(int)((MASK_N_ + 255) / 256), 256>>>(maskRaw);

    // fused QKV projections (2 CTAs/SM)
    gemm_tc<<<dim3(4, 64, 3), 256>>>(iQ, iK, iV, WQ, WK, WV, nullptr, gq, gk, gv, 0);

    // fused attention (exact R14 config)
    const int smemBytes = (32 * SP + 256 * 68 + 32 * 68 + 32 * 9 + 32) * 4;  // 211232
    cudaFuncSetAttribute(attn_kernel, cudaFuncAttributeMaxDynamicSharedMemorySize, smemBytes);
    attn_kernel<<<dim3(32, 8, 8), 512, smemBytes>>>(gq, gk, gv, out_attn, gctx);

    // output projection + residual (2 CTAs/SM, single wave)
    gemm_tc<<<dim3(4, 64, 1), 256>>>(gctx, nullptr, nullptr, Wfc, nullptr, nullptr,
                                     iQ, gpre, nullptr, nullptr, 1);

    ln_kernel<<<8192, 128>>>(gpre, gam, bet, out_ln);
}

// round 17
// speedup vs baseline: 1.1459x; 1.0098x over previous
#include <cuda_runtime.h>
#include <cuda_bf16.h>
#include <cstdint>

#define B_   8
#define S_   1024
#define DM_  512
#define H_   8
#define DK_  64
#define SP   1028   // sS row stride in words

static const size_t ROWS_   = (size_t)B_ * S_;
static const size_t LN_N_   = ROWS_ * DM_;
static const size_t ATTN_N_ = (size_t)B_*H_*S_*S_;
static const size_t MASK_N_ = (size_t)B_*S_*S_;

// ---------------- device scratch ----------------------------------------------
__device__ float g_Q  [8192*512];
__device__ float g_K  [8192*512];
__device__ float g_V  [8192*512];
__device__ float g_ctx[8192*512];
__device__ float g_pre[8192*512];
__device__ float g_attn_scratch[67108864ull];
__device__ unsigned char g_mask[8*1024*1024];
__device__ int g_mask_is_u8;

// ---------------- helpers ------------------------------------------------------
__device__ __forceinline__ uint32_t f2tf(float f) {
    uint32_t r;
    asm("cvt.rna.tf32.f32 %0, %1;" : "=r"(r) : "f"(f));
    return r;
}
__device__ __forceinline__ uint32_t s2u(const void* p) {
    uint32_t a;
    asm("{ .reg .u64 t; cvta.to.shared.u64 t, %1; cvt.u32.u64 %0, t; }"
        : "=r"(a) : "l"(p));
    return a;
}
__device__ __forceinline__ void cpa(uint32_t dst, const float* src) {
    asm volatile("cp.async.cg.shared.global [%0], [%1], 16;" :: "r"(dst), "l"(src));
}
#define CPA_COMMIT() asm volatile("cp.async.commit_group;")

__device__ __forceinline__ void mma8(float* c, const uint32_t* a, uint32_t b0, uint32_t b1) {
    asm volatile("mma.sync.aligned.m16n8k8.row.col.f32.tf32.tf32.f32 "
        "{%0,%1,%2,%3}, {%4,%5,%6,%7}, {%8,%9}, {%0,%1,%2,%3};"
        : "+f"(c[0]), "+f"(c[1]), "+f"(c[2]), "+f"(c[3])
        : "r"(a[0]), "r"(a[1]), "r"(a[2]), "r"(a[3]), "r"(b0), "r"(b1));
}

// ---------------- mask dtype detection + normalization ------------------------
__global__ void mask_detect_kernel(const unsigned char* __restrict__ m) {
    __shared__ int cnt;
    if (threadIdx.x == 0) cnt = 0;
    __syncthreads();
    int local = 0;
    for (int i = threadIdx.x; i < 65536; i += 256)
        if ((i & 3) && __ldg(&m[i])) local++;
    if (local) atomicAdd(&cnt, local);
    __syncthreads();
    if (threadIdx.x == 0) g_mask_is_u8 = (cnt > 0) ? 1 : 0;
}

__global__ void mask_convert_kernel(const unsigned char* __restrict__ m) {
    const int u8 = g_mask_is_u8;
    size_t i = (size_t)blockIdx.x * blockDim.x + threadIdx.x;
    if (i < MASK_N_) {
        if (u8) g_mask[i] = (__ldg(&m[i]) != 0);
        else    g_mask[i] = (__ldg(&((const int*)m)[i]) != 0);
    }
}

// ---------------- tf32 tensor-core GEMM, 2 CTAs/SM (R16, unchanged) -----------
__global__ __launch_bounds__(256, 2)
void gemm_tc(const float* __restrict__ A0, const float* __restrict__ A1, const float* __restrict__ A2,
             const float* __restrict__ B0, const float* __restrict__ B1, const float* __restrict__ B2,
             const float* __restrict__ R,
             float* __restrict__ C0, float* __restrict__ C1, float* __restrict__ C2,
             int addResid)
{
    const float* A  = (blockIdx.z == 0) ? A0 : (blockIdx.z == 1) ? A1 : A2;
    const float* Bm = (blockIdx.z == 0) ? B0 : (blockIdx.z == 1) ? B1 : B2;
    float*       C  = (blockIdx.z == 0) ? C0 : (blockIdx.z == 1) ? C1 : C2;

    __shared__ uint32_t As[128 * 36];
    __shared__ uint32_t Bs[32 * 132];
    const int t = threadIdx.x;
    const int w = t >> 5, lane = t & 31, gid = lane >> 2, tid4 = lane & 3;
    const int wm = w & 1, wn = w >> 1;
    const int brow = blockIdx.y * 128, bcol = blockIdx.x * 128;

    float acc[4][4][4];
    #pragma unroll
    for (int mt = 0; mt < 4; mt++)
        #pragma unroll
        for (int nt = 0; nt < 4; nt++)
            #pragma unroll
            for (int i = 0; i < 4; i++) acc[mt][nt][i] = 0.f;

    float4 va[4], vb[4];
    #pragma unroll
    for (int i = 0; i < 4; i++) {
        int idx = i * 256 + t;
        int m = idx >> 3, k4 = (idx & 7) * 4;
        va[i] = *(const float4*)&A[(size_t)(brow + m) * 512 + k4];
        int kr = idx >> 5, nc = (idx & 31) * 4;
        vb[i] = *(const float4*)&Bm[(size_t)kr * 512 + bcol + nc];
    }

    for (int k0 = 0; k0 < 512; k0 += 32) {
        #pragma unroll
        for (int i = 0; i < 4; i++) {
            int idx = i * 256 + t;
            int m = idx >> 3, k4 = (idx & 7) * 4;
            *(uint4*)&As[m * 36 + k4] =
                make_uint4(f2tf(va[i].x), f2tf(va[i].y), f2tf(va[i].z), f2tf(va[i].w));
            int kr = idx >> 5, nc = (idx & 31) * 4;
            *(uint4*)&Bs[kr * 132 + nc] =
                make_uint4(f2tf(vb[i].x), f2tf(vb[i].y), f2tf(vb[i].z), f2tf(vb[i].w));
        }
        __syncthreads();
        if (k0 + 32 < 512) {
            #pragma unroll
            for (int i = 0; i < 4; i++) {
                int idx = i * 256 + t;
                int m = idx >> 3, k4 = (idx & 7) * 4;
                va[i] = *(const float4*)&A[(size_t)(brow + m) * 512 + k0 + 32 + k4];
                int kr = idx >> 5, nc = (idx & 31) * 4;
                vb[i] = *(const float4*)&Bm[(size_t)(k0 + 32 + kr) * 512 + bcol + nc];
            }
        }
        #pragma unroll
        for (int kk = 0; kk < 4; kk++) {
            const int kb = kk * 8;
            uint32_t af[4][4];
            #pragma unroll
            for (int mt = 0; mt < 4; mt++) {
                int row = wm * 64 + mt * 16 + gid;
                af[mt][0] = As[row * 36 + kb + tid4];
                af[mt][1] = As[(row + 8) * 36 + kb + tid4];
                af[mt][2] = As[row * 36 + kb + tid4 + 4];
                af[mt][3] = As[(row + 8) * 36 + kb + tid4 + 4];
            }
            uint32_t bf[4][2];
            #pragma unroll
            for (int nt = 0; nt < 4; nt++) {
                int n = wn * 32 + nt * 8 + gid;
                bf[nt][0] = Bs[(kb + tid4) * 132 + n];
                bf[nt][1] = Bs[(kb + tid4 + 4) * 132 + n];
            }
            #pragma unroll
            for (int mt = 0; mt < 4; mt++)
                #pragma unroll
                for (int nt = 0; nt < 4; nt++)
                    mma8(acc[mt][nt], af[mt], bf[nt][0], bf[nt][1]);
        }
        __syncthreads();
    }

    #pragma unroll
    for (int mt = 0; mt < 4; mt++) {
        #pragma unroll
        for (int nt = 0; nt < 4; nt++) {
            size_t row = (size_t)(brow + wm * 64 + mt * 16 + gid);
            size_t col = (size_t)(bcol + wn * 32 + nt * 8 + 2 * tid4);
            float2 v0 = make_float2(acc[mt][nt][0], acc[mt][nt][1]);
            float2 v1 = make_float2(acc[mt][nt][2], acc[mt][nt][3]);
            if (addResid) {
                float2 r0 = *(const float2*)&R[row * 512 + col];
                float2 r1 = *(const float2*)&R[(row + 8) * 512 + col];
                v0.x += r0.x; v0.y += r0.y; v1.x += r1.x; v1.y += r1.y;
            }
            *(float2*)&C[row * 512 + col] = v0;
            *(float2*)&C[(row + 8) * 512 + col] = v1;
        }
    }
}

// ---------------- fused attention v10: cp.async double-buffered pipeline ------
// block = (b, h, 32 q rows), 512 threads / 16 warps, 1 CTA/SM
// K and V stream through 2x[128][68] buffers (cp.async.cg, 16B), chunk n+2
// issued after chunk n's compute barrier -> fill latency overlapped.
// Phase 1: S=QK^T tf32 (K raw-bit tf32), exp, rowsums, E stored fp32 in sS
// Phase 2: attn = E*rinv (exact fp32 STG) + f2tf in-place for phase 3
// Phase 3: ctx = P@V tf32 mma8 (V raw-bit tf32), 16x32 tiles, 4-way kq split
// smem: sS 131584 + 2*34816 + sQ 8704 + sums 1312 = 211232 B
__global__ __launch_bounds__(512)
void attn_kernel(const float* __restrict__ Q, const float* __restrict__ K,
                 const float* __restrict__ V,
                 float* __restrict__ attn, float* __restrict__ ctx)
{
    extern __shared__ float sm[];
    float*    sS  = sm;                               // 32*1028 fp32 E -> tf32 P
    uint32_t* sSu = (uint32_t*)sm;
    uint32_t* sKV = (uint32_t*)(sm + 32 * SP);        // 2 x [128][68]
    uint32_t* sQ  = sKV + 2 * 128 * 68;               // [32][68]
    float*    sSum  = (float*)(sQ + 32 * 68);         // [32][9]
    float*    sRinv = sSum + 32 * 9;                  // [32]
    float*    sRed  = (float*)sKV;                    // reduce overlay (26112 B)

    const int t = threadIdx.x;
    const int w = t >> 5, lane = t & 31, gid = lane >> 2, t4 = lane & 3;
    const int b = blockIdx.z, h = blockIdx.y;
    const int q0 = blockIdx.x * 32;
    const size_t rowbase = (size_t)b * 1024;
    const float* Qb = Q + (rowbase + q0) * 512 + h * 64;
    const float* Kb = K + rowbase * 512 + h * 64;
    const float* Vb = V + rowbase * 512 + h * 64;
    const unsigned char* mb = g_mask + ((size_t)b * 1024 + q0) * 1024;
    const uint32_t kvaddr = s2u(sKV);

    // load Q tile 32x64 -> tf32 (rna)
    {
        int r = t >> 4, j = (t & 15) * 4;
        float4 v = *(const float4*)&Qb[(size_t)r * 512 + j];
        *(uint4*)&sQ[r * 68 + j] = make_uint4(f2tf(v.x), f2tf(v.y), f2tf(v.z), f2tf(v.w));
    }
    // prime K chunks 0,1 via cp.async (no dependency on sQ barrier)
    #pragma unroll
    for (int c = 0; c < 2; c++) {
        const float* g = Kb + (size_t)(c * 128) * 512;
        uint32_t base = kvaddr + c * (128 * 68 * 4);
        #pragma unroll
        for (int p = 0; p < 4; p++) {
            int idx = p * 512 + t;
            int r = idx >> 4, j = (idx & 15) * 4;
            cpa(base + (uint32_t)(r * 68 + j) * 4, g + (size_t)r * 512 + j);
        }
        CPA_COMMIT();
    }
    __syncthreads();   // sQ visible

    const int wm = w & 1;      // 16-row half
    const int wn = w >> 1;     // 0..7, 16-col slice (phase 1)
    const int arow = wm * 16 + gid;
    float rs0 = 0.f, rs1 = 0.f;

    // ---- Phase 1: 8 chunks of 128 kv, double-buffered ----
    for (int ch = 0; ch < 8; ch++) {
        if (ch == 7) asm volatile("cp.async.wait_group 0;");
        else         asm volatile("cp.async.wait_group 1;");
        __syncthreads();
        const uint32_t* sK = sKV + (ch & 1) * (128 * 68);
        const int s0 = ch * 128;

        uchar2 mk0[2], mk1[2];
        #pragma unroll
        for (int nt = 0; nt < 2; nt++) {
            int col = s0 + wn * 16 + nt * 8 + 2 * t4;
            mk0[nt] = *(const uchar2*)&mb[(size_t)arow * 1024 + col];
            mk1[nt] = *(const uchar2*)&mb[(size_t)(arow + 8) * 1024 + col];
        }
        float acc[2][4];
        #pragma unroll
        for (int nt = 0; nt < 2; nt++)
            #pragma unroll
            for (int i = 0; i < 4; i++) acc[nt][i] = 0.f;
        #pragma unroll
        for (int ks = 0; ks < 8; ks++) {
            const int k0 = ks * 8;
            uint32_t af[4];
            af[0] = sQ[arow * 68 + k0 + t4];
            af[1] = sQ[(arow + 8) * 68 + k0 + t4];
            af[2] = sQ[arow * 68 + k0 + t4 + 4];
            af[3] = sQ[(arow + 8) * 68 + k0 + t4 + 4];
            #pragma unroll
            for (int nt = 0; nt < 2; nt++) {
                int n = wn * 16 + nt * 8 + gid;
                uint32_t b0 = sK[n * 68 + k0 + t4];
                uint32_t b1 = sK[n * 68 + k0 + t4 + 4];
                mma8(acc[nt], af, b0, b1);
            }
        }
        #pragma unroll
        for (int nt = 0; nt < 2; nt++) {
            int col = s0 + wn * 16 + nt * 8 + 2 * t4;
            float e0 = mk0[nt].x ? 0.f : __expf(acc[nt][0] * 0.125f);
            float e1 = mk0[nt].y ? 0.f : __expf(acc[nt][1] * 0.125f);
            float e2 = mk1[nt].x ? 0.f : __expf(acc[nt][2] * 0.125f);
            float e3 = mk1[nt].y ? 0.f : __expf(acc[nt][3] * 0.125f);
            rs0 += e0 + e1;
            rs1 += e2 + e3;
            *(float2*)&sS[arow * SP + col]       = make_float2(e0, e1);
            *(float2*)&sS[(arow + 8) * SP + col] = make_float2(e2, e3);
        }
        __syncthreads();   // compute done; safe to overwrite buffer (ch&1)
        if (ch + 2 < 8) {
            const float* g = Kb + (size_t)((ch + 2) * 128) * 512;
            uint32_t base = kvaddr + (ch & 1) * (128 * 68 * 4);
            #pragma unroll
            for (int p = 0; p < 4; p++) {
                int idx = p * 512 + t;
                int r = idx >> 4, j = (idx & 15) * 4;
                cpa(base + (uint32_t)(r * 68 + j) * 4, g + (size_t)r * 512 + j);
            }
            CPA_COMMIT();
        }
    }
    // prime V chunks 0,1 (overlaps rowsum + normalize passes)
    #pragma unroll
    for (int c = 0; c < 2; c++) {
        const float* g = Vb + (size_t)(c * 128) * 512;
        uint32_t base = kvaddr + c * (128 * 68 * 4);
        #pragma unroll
        for (int p = 0; p < 4; p++) {
            int idx = p * 512 + t;
            int r = idx >> 4, j = (idx & 15) * 4;
            cpa(base + (uint32_t)(r * 68 + j) * 4, g + (size_t)r * 512 + j);
        }
        CPA_COMMIT();
    }

    // ---- row sums ----
    rs0 += __shfl_xor_sync(0xffffffffu, rs0, 1);
    rs0 += __shfl_xor_sync(0xffffffffu, rs0, 2);
    rs1 += __shfl_xor_sync(0xffffffffu, rs1, 1);
    rs1 += __shfl_xor_sync(0xffffffffu, rs1, 2);
    if (t4 == 0) {
        // phase-1 wn is 0..7 per (wm, gid) row-pair owner set; 8 partials per row
        sSum[arow * 9 + wn]       = rs0;
        sSum[(arow + 8) * 9 + wn] = rs1;
    }
    __syncthreads();
    if (t < 32) {
        float s = 0.f;
        #pragma unroll
        for (int j = 0; j < 8; j++) s += sSum[t * 9 + j];
        sRinv[t] = 1.0f / s;
    }
    __syncthreads();

    // ---- Phase 2: attn = E*rinv (exact fp32) + f2tf in-place ----
    #pragma unroll
    for (int ri = 0; ri < 2; ri++) {
        int r = w * 2 + ri;
        float rv = sRinv[r];
        float* srow = &sS[r * SP];
        uint32_t* srowu = &sSu[r * SP];
        float* arowp = attn + ((size_t)(b * 8 + h) * 1024 + q0 + r) * 1024;
        #pragma unroll
        for (int j = 0; j < 8; j++) {
            int c4 = lane + j * 32;
            float4 v = *(float4*)&srow[c4 * 4];
            v.x *= rv; v.y *= rv; v.z *= rv; v.w *= rv;
            *(float4*)&arowp[c4 * 4] = v;
            *(uint4*)&srowu[c4 * 4] =
                make_uint4(f2tf(v.x), f2tf(v.y), f2tf(v.z), f2tf(v.w));
        }
    }

    // ---- Phase 3: ctx = P@V, tf32 mma8, 8 chunks double-buffered ----
    {
        const int wn3 = (w >> 1) & 1;  // 32-col half of 64
        const int kq  = w >> 2;        // 32-kv quarter of each 128-chunk
        float acc2[4][4];
        #pragma unroll
        for (int nt = 0; nt < 4; nt++)
            #pragma unroll
            for (int i = 0; i < 4; i++) acc2[nt][i] = 0.f;

        for (int ch = 0; ch < 8; ch++) {
            if (ch == 7) asm volatile("cp.async.wait_group 0;");
            else         asm volatile("cp.async.wait_group 1;");
            __syncthreads();   // V visible; also fences phase-2 sS writes (ch=0)
            const uint32_t* sV = sKV + (ch & 1) * (128 * 68);
            #pragma unroll
            for (int ks = 0; ks < 4; ks++) {
                const int kc = ch * 128 + kq * 32 + ks * 8;   // sS column
                const int kl = kq * 32 + ks * 8;              // sV row
                uint32_t af[4];
                af[0] = sSu[arow * SP + kc + t4];
                af[1] = sSu[(arow + 8) * SP + kc + t4];
                af[2] = sSu[arow * SP + kc + t4 + 4];
                af[3] = sSu[(arow + 8) * SP + kc + t4 + 4];
                #pragma unroll
                for (int nt = 0; nt < 4; nt++) {
                    int n = wn3 * 32 + nt * 8 + gid;
                    uint32_t b0 = sV[(kl + t4) * 68 + n];
                    uint32_t b1 = sV[(kl + t4 + 4) * 68 + n];
                    mma8(acc2[nt], af, b0, b1);
                }
            }
            __syncthreads();
            if (ch + 2 < 8) {
                const float* g = Vb + (size_t)((ch + 2) * 128) * 512;
                uint32_t base = kvaddr + (ch & 1) * (128 * 68 * 4);
                #pragma unroll
                for (int p = 0; p < 4; p++) {
                    int idx = p * 512 + t;
                    int r = idx >> 4, j = (idx & 15) * 4;
                    cpa(base + (uint32_t)(r * 68 + j) * 4, g + (size_t)r * 512 + j);
                }
                CPA_COMMIT();
            }
        }
        __syncthreads();
        // reduce 4 kq quarters
        if (kq > 0) {
            int slot = ((kq - 1) * 4 + wm * 2 + wn3) * 544 + lane * 17;
            #pragma unroll
            for (int nt = 0; nt < 4; nt++)
                #pragma unroll
                for (int i = 0; i < 4; i++)
                    sRed[slot + nt * 4 + i] = acc2[nt][i];
        }
        __syncthreads();
        if (kq == 0) {
            #pragma unroll
            for (int q = 1; q < 4; q++) {
                int slot = ((q - 1) * 4 + wm * 2 + wn3) * 544 + lane * 17;
                #pragma unroll
                for (int nt = 0; nt < 4; nt++)
                    #pragma unroll
                    for (int i = 0; i < 4; i++)
                        acc2[nt][i] += sRed[slot + nt * 4 + i];
            }
            float* cb = ctx + (rowbase + q0) * 512 + h * 64;
            #pragma unroll
            for (int nt = 0; nt < 4; nt++) {
                int col = wn3 * 32 + nt * 8 + 2 * t4;
                *(float2*)&cb[(size_t)arow * 512 + col] =
                    make_float2(acc2[nt][0], acc2[nt][1]);
                *(float2*)&cb[(size_t)(arow + 8) * 512 + col] =
                    make_float2(acc2[nt][2], acc2[nt][3]);
            }
        }
    }
}

// ---------------- LayerNorm -----------------------------------------------------
__global__ __launch_bounds__(128)
void ln_kernel(const float* __restrict__ X, const float* __restrict__ gamma,
               const float* __restrict__ beta, float* __restrict__ out)
{
    __shared__ float red[8];
    const int row = blockIdx.x, t = threadIdx.x;
    const float* x = X + (size_t)row * 512;
    float4 v = *(const float4*)&x[t * 4];
    float s  = (v.x + v.y) + (v.z + v.w);
    float s2 = v.x * v.x + v.y * v.y + v.z * v.z + v.w * v.w;
    #pragma unroll
    for (int o = 16; o > 0; o >>= 1) {
        s  += __shfl_xor_sync(0xffffffffu, s,  o);
        s2 += __shfl_xor_sync(0xffffffffu, s2, o);
    }
    const int warp = t >> 5, lane = t & 31;
    if (lane == 0) { red[warp] = s; red[4 + warp] = s2; }
    __syncthreads();
    s  = red[0] + red[1] + red[2] + red[3];
    s2 = red[4] + red[5] + red[6] + red[7];
    float mean = s * (1.0f / 512.0f);
    float var  = s2 * (1.0f / 512.0f) - mean * mean;
    float rstd = rsqrtf(var + 1e-5f);
    float4 gv = *(const float4*)&gamma[t * 4];
    float4 bv = *(const float4*)&beta[t * 4];
    float4 o4;
    o4.x = (v.x - mean) * rstd * gv.x + bv.x;
    o4.y = (v.y - mean) * rstd * gv.y + bv.y;
    o4.z = (v.z - mean) * rstd * gv.z + bv.z;
    o4.w = (v.w - mean) * rstd * gv.w + bv.w;
    *(float4*)&out[(size_t)row * 512 + t * 4] = o4;
}

// ---------------- launch ------------------------------------------------------
extern "C" void kernel_launch(void* const* d_in, const int* in_sizes, int n_in,
                              void* d_out, int out_size)
{
    const float* iQ   = (const float*)d_in[0];
    const float* iK   = (const float*)d_in[1];
    const float* iV   = (const float*)d_in[2];
    const unsigned char* maskRaw = (const unsigned char*)d_in[3];
    const float* WQ   = (const float*)d_in[4];
    const float* WK   = (const float*)d_in[5];
    const float* WV   = (const float*)d_in[6];
    const float* Wfc  = (const float*)d_in[7];
    const float* gam  = (const float*)d_in[8];
    const float* bet  = (const float*)d_in[9];

    float *gq, *gk, *gv, *gctx, *gpre, *gattn;
    cudaGetSymbolAddress((void**)&gq,    g_Q);
    cudaGetSymbolAddress((void**)&gk,    g_K);
    cudaGetSymbolAddress((void**)&gv,    g_V);
    cudaGetSymbolAddress((void**)&gctx,  g_ctx);
    cudaGetSymbolAddress((void**)&gpre,  g_pre);
    cudaGetSymbolAddress((void**)&gattn, g_attn_scratch);

    float* out = (float*)d_out;
    float* out_ln;
    float* out_attn;
    size_t os = (size_t)out_size;
    if (os >= LN_N_ + ATTN_N_)      { out_ln = out;   out_attn = out + LN_N_; }
    else if (os == ATTN_N_)         { out_attn = out; out_ln = gq; }
    else                            { out_ln = out;   out_attn = gattn; }

    mask_detect_kernel<<<1, 256>>>(maskRaw);
    mask_convert_kernel<<<(int)((MASK_N_ + 255) / 256), 256>>>(maskRaw);

    // fused QKV projections (2 CTAs/SM)
    gemm_tc<<<dim3(4, 64, 3), 256>>>(iQ, iK, iV, WQ, WK, WV, nullptr, gq, gk, gv, 0);

    // fused attention (cp.async pipelined)
    const int smemBytes = (32 * SP + 2 * 128 * 68 + 32 * 68 + 32 * 9 + 32) * 4;  // 211232
    cudaFuncSetAttribute(attn_kernel, cudaFuncAttributeMaxDynamicSharedMemorySize, smemBytes);
    attn_kernel<<<dim3(32, 8, 8), 512, smemBytes>>>(gq, gk, gv, out_attn, gctx);

    // output projection + residual (2 CTAs/SM, single wave)
    gemm_tc<<<dim3(4, 64, 1), 256>>>(gctx, nullptr, nullptr, Wfc, nullptr, nullptr,
                                     iQ, gpre, nullptr, nullptr, 1);

    ln_kernel<<<8192, 128>>>(gpre, gam, bet, out_ln);
}